// round 4
// baseline (speedup 1.0000x reference)
#include <cuda_runtime.h>
#include <cuda_fp16.h>
#include <cstdint>

#define OUT_F  4096
#define IN_F   4096
#define TOKENS 8192

// Device scratch (allocation-free rules): dequantized W (32 MB) + fp16 x (64 MB).
__device__ __half g_W[(size_t)OUT_F * IN_F];
__device__ __half g_A[(size_t)TOKENS * IN_F];

// ---------------------------------------------------------------------------
// Kernel 0: convert harness fp32 activations -> fp16.  8 elems / thread.
// ---------------------------------------------------------------------------
__global__ void convert_x_kernel(const float* __restrict__ x) {
    size_t i = ((size_t)blockIdx.x * blockDim.x + threadIdx.x) * 8;
    float4 f0 = *reinterpret_cast<const float4*>(x + i);
    float4 f1 = *reinterpret_cast<const float4*>(x + i + 4);
    __half h[8];
    h[0] = __float2half(f0.x); h[1] = __float2half(f0.y);
    h[2] = __float2half(f0.z); h[3] = __float2half(f0.w);
    h[4] = __float2half(f1.x); h[5] = __float2half(f1.y);
    h[6] = __float2half(f1.z); h[7] = __float2half(f1.w);
    *reinterpret_cast<uint4*>(g_A + i) = *reinterpret_cast<uint4*>(h);
}

// ---------------------------------------------------------------------------
// Kernel 1: NF4-style dequant.  Each thread handles 4 packed bytes -> 8 halves.
// elem 2j = byte j low nibble, 2j+1 = upper.  b1 = elem/64 = j/32; b2 = j/128.
// ---------------------------------------------------------------------------
__global__ void dequant_kernel(const int* __restrict__ qw,
                               const int* __restrict__ absmax,
                               const float* __restrict__ code,
                               const float* __restrict__ offset,
                               const float* __restrict__ s2a,
                               const float* __restrict__ s2c) {
    int j4 = blockIdx.x * blockDim.x + threadIdx.x;   // group of 4 bytes
    int j  = j4 << 2;                                 // first byte index
    int4 q = reinterpret_cast<const int4*>(qw)[j4];
    int b1 = j >> 5;
    int b2 = j >> 7;
    float scale = ((float)absmax[b1] / code[b1]) * (s2a[b2] / s2c[b2]);
    float off   = offset[b1];
    int v[4] = {q.x, q.y, q.z, q.w};
    __half out[8];
#pragma unroll
    for (int t = 0; t < 4; ++t) {
        out[2 * t]     = __float2half(((float)(v[t] & 15)        - off) * scale);
        out[2 * t + 1] = __float2half(((float)((v[t] >> 4) & 15) - off) * scale);
    }
    reinterpret_cast<uint4*>(g_W)[j4] = *reinterpret_cast<uint4*>(out);
}

// ---------------------------------------------------------------------------
// Kernel 2: fp16 GEMM  C[M,N] = A[M,K] * W^T, fp32 output.
// 128x128x64 CTA tile, 3-stage cp.async pipeline, SW128 swizzled smem.
// ---------------------------------------------------------------------------
#define BM 128
#define BN 128
#define BK 64
#define STAGES 3
#define NTHREADS 256
#define TILE_BYTES (BM * BK * 2)   // 16 KB per operand per stage

__device__ __forceinline__ uint32_t sw128(uint32_t b) {
    return b ^ ((b >> 3) & 0x70);
}

__global__ __launch_bounds__(NTHREADS, 1)
void gemm_kernel(float* __restrict__ C) {
    extern __shared__ char smem[];
    const int tid    = threadIdx.x;
    const int lane   = tid & 31;
    const int wid    = tid >> 5;
    const int warp_m = wid >> 2;   // 0..1  -> 64-row slab
    const int warp_n = wid & 3;    // 0..3  -> 32-col slab
    const int bm = blockIdx.y, bn = blockIdx.x;

    const __half* Ablk = g_A + (size_t)bm * BM * IN_F;
    const __half* Bblk = g_W + (size_t)bn * BN * IN_F;

    uint32_t sA_base = (uint32_t)__cvta_generic_to_shared(smem);
    uint32_t sB_base = sA_base + STAGES * TILE_BYTES;

    const int ldrow   = tid >> 3;  // 0..31
    const int ldchunk = tid & 7;   // 16B chunk within 128B row

    float acc[4][4][4];
#pragma unroll
    for (int mi = 0; mi < 4; ++mi)
#pragma unroll
        for (int ni = 0; ni < 4; ++ni)
#pragma unroll
            for (int t = 0; t < 4; ++t) acc[mi][ni][t] = 0.f;

    auto load_stage = [&](int stage, int kt) {
        uint32_t a_s = sA_base + stage * TILE_BYTES;
        uint32_t b_s = sB_base + stage * TILE_BYTES;
        int k0 = kt * BK;
#pragma unroll
        for (int r = 0; r < 4; ++r) {
            int row = ldrow + r * 32;
            uint32_t soff = sw128((uint32_t)(row * 128 + ldchunk * 16));
            const void* ga = Ablk + (size_t)row * IN_F + k0 + ldchunk * 8;
            const void* gb = Bblk + (size_t)row * IN_F + k0 + ldchunk * 8;
            asm volatile("cp.async.cg.shared.global [%0], [%1], 16;\n"
                         :: "r"(a_s + soff), "l"(ga));
            asm volatile("cp.async.cg.shared.global [%0], [%1], 16;\n"
                         :: "r"(b_s + soff), "l"(gb));
        }
    };

    const int k_tiles = IN_F / BK;   // 64

#pragma unroll
    for (int s = 0; s < STAGES - 1; ++s) {
        load_stage(s, s);
        asm volatile("cp.async.commit_group;\n");
    }

    for (int kt = 0; kt < k_tiles; ++kt) {
        asm volatile("cp.async.wait_group %0;\n" :: "n"(STAGES - 2));
        __syncthreads();

        int nkt = kt + STAGES - 1;
        if (nkt < k_tiles) load_stage(nkt % STAGES, nkt);
        asm volatile("cp.async.commit_group;\n");

        uint32_t a_s = sA_base + (kt % STAGES) * TILE_BYTES;
        uint32_t b_s = sB_base + (kt % STAGES) * TILE_BYTES;

#pragma unroll
        for (int ks = 0; ks < BK / 16; ++ks) {
            uint32_t a_frag[4][4];
            uint32_t b_frag[4][2];
            int colh = ks * 16 + ((lane >> 4) & 1) * 8;   // 8-half column base
#pragma unroll
            for (int mi = 0; mi < 4; ++mi) {
                int row = warp_m * 64 + mi * 16 + (lane & 15);
                uint32_t addr = a_s + sw128((uint32_t)(row * 128 + colh * 2));
                asm volatile(
                    "ldmatrix.sync.aligned.m8n8.x4.shared.b16 {%0,%1,%2,%3}, [%4];\n"
                    : "=r"(a_frag[mi][0]), "=r"(a_frag[mi][1]),
                      "=r"(a_frag[mi][2]), "=r"(a_frag[mi][3])
                    : "r"(addr));
            }
#pragma unroll
            for (int ng = 0; ng < 2; ++ng) {
                int row = warp_n * 32 + ng * 16 + (lane & 15);
                uint32_t addr = b_s + sw128((uint32_t)(row * 128 + colh * 2));
                uint32_t r0, r1, r2, r3;
                asm volatile(
                    "ldmatrix.sync.aligned.m8n8.x4.shared.b16 {%0,%1,%2,%3}, [%4];\n"
                    : "=r"(r0), "=r"(r1), "=r"(r2), "=r"(r3)
                    : "r"(addr));
                b_frag[2 * ng][0]     = r0;
                b_frag[2 * ng + 1][0] = r1;
                b_frag[2 * ng][1]     = r2;
                b_frag[2 * ng + 1][1] = r3;
            }
#pragma unroll
            for (int mi = 0; mi < 4; ++mi)
#pragma unroll
                for (int ni = 0; ni < 4; ++ni) {
                    asm volatile(
                        "mma.sync.aligned.m16n8k16.row.col.f32.f16.f16.f32 "
                        "{%0,%1,%2,%3}, {%4,%5,%6,%7}, {%8,%9}, {%0,%1,%2,%3};\n"
                        : "+f"(acc[mi][ni][0]), "+f"(acc[mi][ni][1]),
                          "+f"(acc[mi][ni][2]), "+f"(acc[mi][ni][3])
                        : "r"(a_frag[mi][0]), "r"(a_frag[mi][1]),
                          "r"(a_frag[mi][2]), "r"(a_frag[mi][3]),
                          "r"(b_frag[ni][0]), "r"(b_frag[ni][1]));
                }
        }
    }

    // epilogue: fp32 accumulators -> float32 output
    float* Cblk = C + (size_t)bm * BM * OUT_F + bn * BN;
#pragma unroll
    for (int mi = 0; mi < 4; ++mi)
#pragma unroll
        for (int ni = 0; ni < 4; ++ni) {
            int r0 = warp_m * 64 + mi * 16 + (lane >> 2);
            int cc = warp_n * 32 + ni * 8 + (lane & 3) * 2;
            float2 v0 = make_float2(acc[mi][ni][0], acc[mi][ni][1]);
            float2 v1 = make_float2(acc[mi][ni][2], acc[mi][ni][3]);
            *reinterpret_cast<float2*>(Cblk + (size_t)r0 * OUT_F + cc)       = v0;
            *reinterpret_cast<float2*>(Cblk + (size_t)(r0 + 8) * OUT_F + cc) = v1;
        }
}

// ---------------------------------------------------------------------------
extern "C" void kernel_launch(void* const* d_in, const int* in_sizes, int n_in,
                              void* d_out, int out_size) {
    const float* x       = (const float*)d_in[0];
    const int*   qw      = (const int*)d_in[1];
    const int*   absmax  = (const int*)d_in[2];
    const float* code    = (const float*)d_in[3];
    const float* offset  = (const float*)d_in[4];
    const float* s2a     = (const float*)d_in[5];
    const float* s2c     = (const float*)d_in[6];
    float* out = (float*)d_out;

    // 0) convert x fp32 -> fp16
    const size_t NA = (size_t)TOKENS * IN_F;           // 33,554,432
    convert_x_kernel<<<(int)(NA / 8 / 256), 256>>>(x);

    // 1) dequantize weights into g_W
    const int P4 = (OUT_F * IN_F / 2) / 4;             // 2,097,152 groups
    dequant_kernel<<<P4 / 256, 256>>>(qw, absmax, code, offset, s2a, s2c);

    // 2) GEMM
    const int smem_bytes = 2 * STAGES * TILE_BYTES;    // 96 KB
    cudaFuncSetAttribute(gemm_kernel,
                         cudaFuncAttributeMaxDynamicSharedMemorySize, smem_bytes);
    dim3 grid(OUT_F / BN, TOKENS / BM);                // (32, 64)
    gemm_kernel<<<grid, NTHREADS, smem_bytes>>>(out);
}

// round 8
// speedup vs baseline: 1.6935x; 1.6935x over previous
#include <cuda_runtime.h>
#include <cuda_fp16.h>
#include <cstdint>

#define OUT_F  4096
#define IN_F   4096
#define TOKENS 8192

// Device scratch: dequantized W (32 MB) + fp16 x (64 MB).
__device__ __align__(256) __half g_W[(size_t)OUT_F * IN_F];
__device__ __align__(256) __half g_A[(size_t)TOKENS * IN_F];

// ---------------------------------------------------------------------------
// Kernel 0: convert fp32 activations -> fp16 (8 elems / thread)
// ---------------------------------------------------------------------------
__global__ void convert_x_kernel(const float* __restrict__ x) {
    size_t i = ((size_t)blockIdx.x * blockDim.x + threadIdx.x) * 8;
    float4 f0 = *reinterpret_cast<const float4*>(x + i);
    float4 f1 = *reinterpret_cast<const float4*>(x + i + 4);
    __half h[8];
    h[0] = __float2half(f0.x); h[1] = __float2half(f0.y);
    h[2] = __float2half(f0.z); h[3] = __float2half(f0.w);
    h[4] = __float2half(f1.x); h[5] = __float2half(f1.y);
    h[6] = __float2half(f1.z); h[7] = __float2half(f1.w);
    *reinterpret_cast<uint4*>(g_A + i) = *reinterpret_cast<uint4*>(h);
}

// ---------------------------------------------------------------------------
// Kernel 1: NF4-style double dequant. 4 packed bytes -> 8 halves per thread.
// ---------------------------------------------------------------------------
__global__ void dequant_kernel(const int* __restrict__ qw,
                               const int* __restrict__ absmax,
                               const float* __restrict__ code,
                               const float* __restrict__ offset,
                               const float* __restrict__ s2a,
                               const float* __restrict__ s2c) {
    int j4 = blockIdx.x * blockDim.x + threadIdx.x;
    int j  = j4 << 2;
    int4 q = reinterpret_cast<const int4*>(qw)[j4];
    int b1 = j >> 5;
    int b2 = j >> 7;
    float scale = ((float)absmax[b1] / code[b1]) * (s2a[b2] / s2c[b2]);
    float off   = offset[b1];
    int v[4] = {q.x, q.y, q.z, q.w};
    __half out[8];
#pragma unroll
    for (int t = 0; t < 4; ++t) {
        out[2 * t]     = __float2half(((float)(v[t] & 15)        - off) * scale);
        out[2 * t + 1] = __float2half(((float)((v[t] >> 4) & 15) - off) * scale);
    }
    reinterpret_cast<uint4*>(g_W)[j4] = *reinterpret_cast<uint4*>(out);
}

// ---------------------------------------------------------------------------
// Kernel 2: fp16 GEMM  C[M,N] = A[M,K] * W^T, fp32 output.
// BM=128, BN=256, BK=64; 8 warps in 2x4, warp tile 64x64.
// 3-stage cp.async pipeline, SW128 swizzled smem.
// ---------------------------------------------------------------------------
#define BM 128
#define BN 256
#define BK 64
#define STAGES 3
#define NTHREADS 256
#define A_BYTES (BM * BK * 2)            // 16 KB
#define B_BYTES (BN * BK * 2)            // 32 KB
#define STAGE_BYTES (A_BYTES + B_BYTES)  // 48 KB

__device__ __forceinline__ uint32_t sw128(uint32_t b) {
    return b ^ ((b >> 3) & 0x70);
}

__global__ __launch_bounds__(NTHREADS, 1)
void gemm_kernel(float* __restrict__ C) {
    extern __shared__ char smem[];
    const int tid    = threadIdx.x;
    const int lane   = tid & 31;
    const int wid    = tid >> 5;
    const int warp_m = wid >> 2;   // 0..1  -> 64-row slab
    const int warp_n = wid & 3;    // 0..3  -> 64-col slab
    const int bm = blockIdx.y, bn = blockIdx.x;

    const __half* Ablk = g_A + (size_t)bm * BM * IN_F;
    const __half* Bblk = g_W + (size_t)bn * BN * IN_F;

    uint32_t s_base = (uint32_t)__cvta_generic_to_shared(smem);

    const int ldrow   = tid >> 3;  // 0..31
    const int ldchunk = tid & 7;   // 16B chunk within 128B row

    float acc[4][8][4];
#pragma unroll
    for (int mi = 0; mi < 4; ++mi)
#pragma unroll
        for (int ni = 0; ni < 8; ++ni)
#pragma unroll
            for (int t = 0; t < 4; ++t) acc[mi][ni][t] = 0.f;

    auto load_stage = [&](int stage, int kt) {
        uint32_t a_s = s_base + stage * STAGE_BYTES;
        uint32_t b_s = a_s + A_BYTES;
        int k0 = kt * BK;
        uint32_t soff0 = (uint32_t)(ldrow * 128 + ldchunk * 16);
#pragma unroll
        for (int r = 0; r < 4; ++r) {   // A: 128 rows in 4 passes of 32
            uint32_t soff = sw128(soff0 + (uint32_t)r * 32 * 128);
            const void* ga = Ablk + (size_t)(ldrow + r * 32) * IN_F + k0 + ldchunk * 8;
            asm volatile("cp.async.cg.shared.global [%0], [%1], 16;\n"
                         :: "r"(a_s + soff), "l"(ga));
        }
#pragma unroll
        for (int r = 0; r < 8; ++r) {   // B: 256 rows in 8 passes of 32
            uint32_t soff = sw128(soff0 + (uint32_t)r * 32 * 128);
            const void* gb = Bblk + (size_t)(ldrow + r * 32) * IN_F + k0 + ldchunk * 8;
            asm volatile("cp.async.cg.shared.global [%0], [%1], 16;\n"
                         :: "r"(b_s + soff), "l"(gb));
        }
    };

    const int k_tiles = IN_F / BK;   // 64

#pragma unroll
    for (int s = 0; s < STAGES - 1; ++s) {
        load_stage(s, s);
        asm volatile("cp.async.commit_group;\n");
    }

    for (int kt = 0; kt < k_tiles; ++kt) {
        asm volatile("cp.async.wait_group %0;\n" :: "n"(STAGES - 2));
        __syncthreads();

        int nkt = kt + STAGES - 1;
        if (nkt < k_tiles) load_stage(nkt % STAGES, nkt);
        asm volatile("cp.async.commit_group;\n");

        uint32_t a_s = s_base + (kt % STAGES) * STAGE_BYTES;
        uint32_t b_s = a_s + A_BYTES;

#pragma unroll
        for (int ks = 0; ks < BK / 16; ++ks) {
            uint32_t a_frag[4][4];
            uint32_t b_frag[8][2];
            int colh = ks * 16 + ((lane >> 4) & 1) * 8;   // 8-half column base
#pragma unroll
            for (int mi = 0; mi < 4; ++mi) {
                int row = warp_m * 64 + mi * 16 + (lane & 15);
                uint32_t addr = a_s + sw128((uint32_t)(row * 128 + colh * 2));
                asm volatile(
                    "ldmatrix.sync.aligned.m8n8.x4.shared.b16 {%0,%1,%2,%3}, [%4];\n"
                    : "=r"(a_frag[mi][0]), "=r"(a_frag[mi][1]),
                      "=r"(a_frag[mi][2]), "=r"(a_frag[mi][3])
                    : "r"(addr));
            }
#pragma unroll
            for (int ng = 0; ng < 4; ++ng) {
                int row = warp_n * 64 + ng * 16 + (lane & 15);
                uint32_t addr = b_s + sw128((uint32_t)(row * 128 + colh * 2));
                uint32_t r0, r1, r2, r3;
                asm volatile(
                    "ldmatrix.sync.aligned.m8n8.x4.shared.b16 {%0,%1,%2,%3}, [%4];\n"
                    : "=r"(r0), "=r"(r1), "=r"(r2), "=r"(r3)
                    : "r"(addr));
                b_frag[2 * ng][0]     = r0;
                b_frag[2 * ng + 1][0] = r1;
                b_frag[2 * ng][1]     = r2;
                b_frag[2 * ng + 1][1] = r3;
            }
#pragma unroll
            for (int mi = 0; mi < 4; ++mi)
#pragma unroll
                for (int ni = 0; ni < 8; ++ni) {
                    asm volatile(
                        "mma.sync.aligned.m16n8k16.row.col.f32.f16.f16.f32 "
                        "{%0,%1,%2,%3}, {%4,%5,%6,%7}, {%8,%9}, {%0,%1,%2,%3};\n"
                        : "+f"(acc[mi][ni][0]), "+f"(acc[mi][ni][1]),
                          "+f"(acc[mi][ni][2]), "+f"(acc[mi][ni][3])
                        : "r"(a_frag[mi][0]), "r"(a_frag[mi][1]),
                          "r"(a_frag[mi][2]), "r"(a_frag[mi][3]),
                          "r"(b_frag[ni][0]), "r"(b_frag[ni][1]));
                }
        }
    }

    // epilogue: fp32 accumulators -> float32 output
    float* Cblk = C + (size_t)bm * BM * OUT_F + bn * BN;
#pragma unroll
    for (int mi = 0; mi < 4; ++mi)
#pragma unroll
        for (int ni = 0; ni < 8; ++ni) {
            int r0 = warp_m * 64 + mi * 16 + (lane >> 2);
            int cc = warp_n * 64 + ni * 8 + (lane & 3) * 2;
            float2 v0 = make_float2(acc[mi][ni][0], acc[mi][ni][1]);
            float2 v1 = make_float2(acc[mi][ni][2], acc[mi][ni][3]);
            *reinterpret_cast<float2*>(Cblk + (size_t)r0 * OUT_F + cc)       = v0;
            *reinterpret_cast<float2*>(Cblk + (size_t)(r0 + 8) * OUT_F + cc) = v1;
        }
}

// ---------------------------------------------------------------------------
extern "C" void kernel_launch(void* const* d_in, const int* in_sizes, int n_in,
                              void* d_out, int out_size) {
    const float* x       = (const float*)d_in[0];
    const int*   qw      = (const int*)d_in[1];
    const int*   absmax  = (const int*)d_in[2];
    const float* code    = (const float*)d_in[3];
    const float* offset  = (const float*)d_in[4];
    const float* s2a     = (const float*)d_in[5];
    const float* s2c     = (const float*)d_in[6];
    float* out = (float*)d_out;

    const size_t NA = (size_t)TOKENS * IN_F;
    convert_x_kernel<<<(int)(NA / 8 / 256), 256>>>(x);

    const int P4 = (OUT_F * IN_F / 2) / 4;
    dequant_kernel<<<P4 / 256, 256>>>(qw, absmax, code, offset, s2a, s2c);

    const int smem_bytes = STAGES * STAGE_BYTES;   // 144 KB
    cudaFuncSetAttribute(gemm_kernel,
                         cudaFuncAttributeMaxDynamicSharedMemorySize, smem_bytes);
    dim3 grid(OUT_F / BN, TOKENS / BM);            // (16, 64)
    gemm_kernel<<<grid, NTHREADS, smem_bytes>>>(out);
}

// round 9
// speedup vs baseline: 1.6948x; 1.0008x over previous
#include <cuda_runtime.h>
#include <cuda_fp16.h>
#include <cstdint>

#define OUT_F  4096
#define IN_F   4096
#define TOKENS 8192

// Device scratch: dequantized W (32 MB) + fp16 x (64 MB).
__device__ __align__(256) __half g_W[(size_t)OUT_F * IN_F];
__device__ __align__(256) __half g_A[(size_t)TOKENS * IN_F];

// ---------------------------------------------------------------------------
// Kernel 0: convert fp32 activations -> fp16 (8 elems / thread)
// ---------------------------------------------------------------------------
__global__ void convert_x_kernel(const float* __restrict__ x) {
    size_t i = ((size_t)blockIdx.x * blockDim.x + threadIdx.x) * 8;
    float4 f0 = *reinterpret_cast<const float4*>(x + i);
    float4 f1 = *reinterpret_cast<const float4*>(x + i + 4);
    __half h[8];
    h[0] = __float2half(f0.x); h[1] = __float2half(f0.y);
    h[2] = __float2half(f0.z); h[3] = __float2half(f0.w);
    h[4] = __float2half(f1.x); h[5] = __float2half(f1.y);
    h[6] = __float2half(f1.z); h[7] = __float2half(f1.w);
    *reinterpret_cast<uint4*>(g_A + i) = *reinterpret_cast<uint4*>(h);
}

// ---------------------------------------------------------------------------
// Kernel 1: NF4-style double dequant. 4 packed bytes -> 8 halves per thread.
// ---------------------------------------------------------------------------
__global__ void dequant_kernel(const int* __restrict__ qw,
                               const int* __restrict__ absmax,
                               const float* __restrict__ code,
                               const float* __restrict__ offset,
                               const float* __restrict__ s2a,
                               const float* __restrict__ s2c) {
    int j4 = blockIdx.x * blockDim.x + threadIdx.x;
    int j  = j4 << 2;
    int4 q = reinterpret_cast<const int4*>(qw)[j4];
    int b1 = j >> 5;
    int b2 = j >> 7;
    float scale = ((float)absmax[b1] / code[b1]) * (s2a[b2] / s2c[b2]);
    float off   = offset[b1];
    int v[4] = {q.x, q.y, q.z, q.w};
    __half out[8];
#pragma unroll
    for (int t = 0; t < 4; ++t) {
        out[2 * t]     = __float2half(((float)(v[t] & 15)        - off) * scale);
        out[2 * t + 1] = __float2half(((float)((v[t] >> 4) & 15) - off) * scale);
    }
    reinterpret_cast<uint4*>(g_W)[j4] = *reinterpret_cast<uint4*>(out);
}

// ---------------------------------------------------------------------------
// Kernel 2: fp16 GEMM  C[M,N] = A[M,K] * W^T, fp32 output.
// BM=128, BN=256, BK=64; 8 warps in 2x4, warp tile 64x64.
// 3-stage cp.async pipeline + double-buffered ldmatrix fragments.
// ---------------------------------------------------------------------------
#define BM 128
#define BN 256
#define BK 64
#define STAGES 3
#define NTHREADS 256
#define A_BYTES (BM * BK * 2)            // 16 KB
#define B_BYTES (BN * BK * 2)            // 32 KB
#define STAGE_BYTES (A_BYTES + B_BYTES)  // 48 KB

__device__ __forceinline__ uint32_t sw128(uint32_t b) {
    return b ^ ((b >> 3) & 0x70);
}

__global__ __launch_bounds__(NTHREADS, 1)
void gemm_kernel(float* __restrict__ C) {
    extern __shared__ char smem[];
    const int tid    = threadIdx.x;
    const int lane   = tid & 31;
    const int wid    = tid >> 5;
    const int warp_m = wid >> 2;   // 0..1  -> 64-row slab
    const int warp_n = wid & 3;    // 0..3  -> 64-col slab
    const int bm = blockIdx.y, bn = blockIdx.x;

    const __half* Ablk = g_A + (size_t)bm * BM * IN_F;
    const __half* Bblk = g_W + (size_t)bn * BN * IN_F;

    uint32_t s_base = (uint32_t)__cvta_generic_to_shared(smem);

    const int ldrow   = tid >> 3;  // 0..31
    const int ldchunk = tid & 7;   // 16B chunk within 128B row

    // per-warp ldmatrix lane addresses (pre-swizzled byte offsets within tile)
    const int a_row = warp_m * 64 + (lane & 15);
    const int b_row = warp_n * 64 + (lane & 15);
    const int colh8 = ((lane >> 4) & 1) * 8;   // 8-half sub-column

    float acc[4][8][4];
#pragma unroll
    for (int mi = 0; mi < 4; ++mi)
#pragma unroll
        for (int ni = 0; ni < 8; ++ni)
#pragma unroll
            for (int t = 0; t < 4; ++t) acc[mi][ni][t] = 0.f;

    auto load_stage = [&](int stage, int kt) {
        uint32_t a_s = s_base + stage * STAGE_BYTES;
        uint32_t b_s = a_s + A_BYTES;
        int k0 = kt * BK;
        uint32_t soff0 = (uint32_t)(ldrow * 128 + ldchunk * 16);
#pragma unroll
        for (int r = 0; r < 4; ++r) {   // A: 128 rows in 4 passes of 32
            uint32_t soff = sw128(soff0 + (uint32_t)r * 32 * 128);
            const void* ga = Ablk + (size_t)(ldrow + r * 32) * IN_F + k0 + ldchunk * 8;
            asm volatile("cp.async.cg.shared.global [%0], [%1], 16;\n"
                         :: "r"(a_s + soff), "l"(ga));
        }
#pragma unroll
        for (int r = 0; r < 8; ++r) {   // B: 256 rows in 8 passes of 32
            uint32_t soff = sw128(soff0 + (uint32_t)r * 32 * 128);
            const void* gb = Bblk + (size_t)(ldrow + r * 32) * IN_F + k0 + ldchunk * 8;
            asm volatile("cp.async.cg.shared.global [%0], [%1], 16;\n"
                         :: "r"(b_s + soff), "l"(gb));
        }
    };

    const int k_tiles = IN_F / BK;   // 64

#pragma unroll
    for (int s = 0; s < STAGES - 1; ++s) {
        load_stage(s, s);
        asm volatile("cp.async.commit_group;\n");
    }

    uint32_t a_frag[2][4][4];
    uint32_t b_frag[2][8][2];

    // fragment loader for one 16-deep k-slice into buffer `buf`
    auto load_frags = [&](uint32_t a_s, uint32_t b_s, int ks, int buf) {
        int colh = ks * 16 + colh8;
#pragma unroll
        for (int mi = 0; mi < 4; ++mi) {
            int row = a_row + mi * 16;
            uint32_t addr = a_s + sw128((uint32_t)(row * 128 + colh * 2));
            asm volatile(
                "ldmatrix.sync.aligned.m8n8.x4.shared.b16 {%0,%1,%2,%3}, [%4];\n"
                : "=r"(a_frag[buf][mi][0]), "=r"(a_frag[buf][mi][1]),
                  "=r"(a_frag[buf][mi][2]), "=r"(a_frag[buf][mi][3])
                : "r"(addr));
        }
#pragma unroll
        for (int ng = 0; ng < 4; ++ng) {
            int row = b_row + ng * 16;
            uint32_t addr = b_s + sw128((uint32_t)(row * 128 + colh * 2));
            uint32_t r0, r1, r2, r3;
            asm volatile(
                "ldmatrix.sync.aligned.m8n8.x4.shared.b16 {%0,%1,%2,%3}, [%4];\n"
                : "=r"(r0), "=r"(r1), "=r"(r2), "=r"(r3)
                : "r"(addr));
            b_frag[buf][2 * ng][0]     = r0;
            b_frag[buf][2 * ng + 1][0] = r1;
            b_frag[buf][2 * ng][1]     = r2;
            b_frag[buf][2 * ng + 1][1] = r3;
        }
    };

    for (int kt = 0; kt < k_tiles; ++kt) {
        asm volatile("cp.async.wait_group %0;\n" :: "n"(STAGES - 2));
        __syncthreads();

        int nkt = kt + STAGES - 1;
        if (nkt < k_tiles) load_stage(nkt % STAGES, nkt);
        asm volatile("cp.async.commit_group;\n");

        uint32_t a_s = s_base + (kt % STAGES) * STAGE_BYTES;
        uint32_t b_s = a_s + A_BYTES;

        load_frags(a_s, b_s, 0, 0);
#pragma unroll
        for (int ks = 0; ks < BK / 16; ++ks) {
            int cur = ks & 1;
            if (ks < BK / 16 - 1) load_frags(a_s, b_s, ks + 1, cur ^ 1);
#pragma unroll
            for (int mi = 0; mi < 4; ++mi)
#pragma unroll
                for (int ni = 0; ni < 8; ++ni) {
                    asm volatile(
                        "mma.sync.aligned.m16n8k16.row.col.f32.f16.f16.f32 "
                        "{%0,%1,%2,%3}, {%4,%5,%6,%7}, {%8,%9}, {%0,%1,%2,%3};\n"
                        : "+f"(acc[mi][ni][0]), "+f"(acc[mi][ni][1]),
                          "+f"(acc[mi][ni][2]), "+f"(acc[mi][ni][3])
                        : "r"(a_frag[cur][mi][0]), "r"(a_frag[cur][mi][1]),
                          "r"(a_frag[cur][mi][2]), "r"(a_frag[cur][mi][3]),
                          "r"(b_frag[cur][ni][0]), "r"(b_frag[cur][ni][1]));
                }
        }
    }

    // epilogue: fp32 accumulators -> float32 output
    float* Cblk = C + (size_t)bm * BM * OUT_F + bn * BN;
#pragma unroll
    for (int mi = 0; mi < 4; ++mi)
#pragma unroll
        for (int ni = 0; ni < 8; ++ni) {
            int r0 = warp_m * 64 + mi * 16 + (lane >> 2);
            int cc = warp_n * 64 + ni * 8 + (lane & 3) * 2;
            float2 v0 = make_float2(acc[mi][ni][0], acc[mi][ni][1]);
            float2 v1 = make_float2(acc[mi][ni][2], acc[mi][ni][3]);
            *reinterpret_cast<float2*>(Cblk + (size_t)r0 * OUT_F + cc)       = v0;
            *reinterpret_cast<float2*>(Cblk + (size_t)(r0 + 8) * OUT_F + cc) = v1;
        }
}

// ---------------------------------------------------------------------------
extern "C" void kernel_launch(void* const* d_in, const int* in_sizes, int n_in,
                              void* d_out, int out_size) {
    const float* x       = (const float*)d_in[0];
    const int*   qw      = (const int*)d_in[1];
    const int*   absmax  = (const int*)d_in[2];
    const float* code    = (const float*)d_in[3];
    const float* offset  = (const float*)d_in[4];
    const float* s2a     = (const float*)d_in[5];
    const float* s2c     = (const float*)d_in[6];
    float* out = (float*)d_out;

    const size_t NA = (size_t)TOKENS * IN_F;
    convert_x_kernel<<<(int)(NA / 8 / 256), 256>>>(x);

    const int P4 = (OUT_F * IN_F / 2) / 4;
    dequant_kernel<<<P4 / 256, 256>>>(qw, absmax, code, offset, s2a, s2c);

    const int smem_bytes = STAGES * STAGE_BYTES;   // 144 KB
    cudaFuncSetAttribute(gemm_kernel,
                         cudaFuncAttributeMaxDynamicSharedMemorySize, smem_bytes);
    dim3 grid(OUT_F / BN, TOKENS / BM);            // (16, 64)
    gemm_kernel<<<grid, NTHREADS, smem_bytes>>>(out);
}

// round 11
// speedup vs baseline: 1.7773x; 1.0487x over previous
#include <cuda_runtime.h>
#include <cuda_fp16.h>
#include <cstdint>

#define OUT_F  4096
#define IN_F   4096
#define TOKENS 8192

// Device scratch: dequantized W (32 MB) + fp16 x (64 MB).
__device__ __align__(256) __half g_W[(size_t)OUT_F * IN_F];
__device__ __align__(256) __half g_A[(size_t)TOKENS * IN_F];

// ---------------------------------------------------------------------------
// Kernel 0: convert fp32 activations -> fp16 (8 elems / thread)
// ---------------------------------------------------------------------------
__global__ void convert_x_kernel(const float* __restrict__ x) {
    size_t i = ((size_t)blockIdx.x * blockDim.x + threadIdx.x) * 8;
    float4 f0 = *reinterpret_cast<const float4*>(x + i);
    float4 f1 = *reinterpret_cast<const float4*>(x + i + 4);
    __half h[8];
    h[0] = __float2half(f0.x); h[1] = __float2half(f0.y);
    h[2] = __float2half(f0.z); h[3] = __float2half(f0.w);
    h[4] = __float2half(f1.x); h[5] = __float2half(f1.y);
    h[6] = __float2half(f1.z); h[7] = __float2half(f1.w);
    *reinterpret_cast<uint4*>(g_A + i) = *reinterpret_cast<uint4*>(h);
}

// ---------------------------------------------------------------------------
// Kernel 1: NF4-style double dequant. 4 packed bytes -> 8 halves per thread.
// ---------------------------------------------------------------------------
__global__ void dequant_kernel(const int* __restrict__ qw,
                               const int* __restrict__ absmax,
                               const float* __restrict__ code,
                               const float* __restrict__ offset,
                               const float* __restrict__ s2a,
                               const float* __restrict__ s2c) {
    int j4 = blockIdx.x * blockDim.x + threadIdx.x;
    int j  = j4 << 2;
    int4 q = reinterpret_cast<const int4*>(qw)[j4];
    int b1 = j >> 5;
    int b2 = j >> 7;
    float scale = ((float)absmax[b1] / code[b1]) * (s2a[b2] / s2c[b2]);
    float off   = offset[b1];
    int v[4] = {q.x, q.y, q.z, q.w};
    __half out[8];
#pragma unroll
    for (int t = 0; t < 4; ++t) {
        out[2 * t]     = __float2half(((float)(v[t] & 15)        - off) * scale);
        out[2 * t + 1] = __float2half(((float)((v[t] >> 4) & 15) - off) * scale);
    }
    reinterpret_cast<uint4*>(g_W)[j4] = *reinterpret_cast<uint4*>(out);
}

// ---------------------------------------------------------------------------
// Kernel 2: fp16 GEMM  C[M,N] = A[M,K] * W^T, fp32 output.
// BM=128, BN=256, BK=64; 16 warps in 4x4, warp tile 32x64 (512 threads).
// 3-stage cp.async pipeline, SW128 swizzled smem.
// ---------------------------------------------------------------------------
#define BM 128
#define BN 256
#define BK 64
#define STAGES 3
#define NTHREADS 512
#define A_BYTES (BM * BK * 2)            // 16 KB
#define B_BYTES (BN * BK * 2)            // 32 KB
#define STAGE_BYTES (A_BYTES + B_BYTES)  // 48 KB

__device__ __forceinline__ uint32_t sw128(uint32_t b) {
    return b ^ ((b >> 3) & 0x70);
}

__global__ __launch_bounds__(NTHREADS, 1)
void gemm_kernel(float* __restrict__ C) {
    extern __shared__ char smem[];
    const int tid    = threadIdx.x;
    const int lane   = tid & 31;
    const int wid    = tid >> 5;
    const int warp_m = wid >> 2;   // 0..3  -> 32-row slab
    const int warp_n = wid & 3;    // 0..3  -> 64-col slab
    const int bm = blockIdx.y, bn = blockIdx.x;

    const __half* Ablk = g_A + (size_t)bm * BM * IN_F;
    const __half* Bblk = g_W + (size_t)bn * BN * IN_F;

    uint32_t s_base = (uint32_t)__cvta_generic_to_shared(smem);

    const int ldrow   = tid >> 3;  // 0..63
    const int ldchunk = tid & 7;   // 16B chunk within 128B row

    const int a_row = warp_m * 32 + (lane & 15);
    const int b_row = warp_n * 64 + (lane & 15);
    const int colh8 = ((lane >> 4) & 1) * 8;   // 8-half sub-column

    float acc[2][8][4];
#pragma unroll
    for (int mi = 0; mi < 2; ++mi)
#pragma unroll
        for (int ni = 0; ni < 8; ++ni)
#pragma unroll
            for (int t = 0; t < 4; ++t) acc[mi][ni][t] = 0.f;

    auto load_stage = [&](int stage, int kt) {
        uint32_t a_s = s_base + stage * STAGE_BYTES;
        uint32_t b_s = a_s + A_BYTES;
        int k0 = kt * BK;
        uint32_t soff0 = (uint32_t)(ldrow * 128 + ldchunk * 16);
#pragma unroll
        for (int r = 0; r < 2; ++r) {   // A: 128 rows in 2 passes of 64
            uint32_t soff = sw128(soff0 + (uint32_t)r * 64 * 128);
            const void* ga = Ablk + (size_t)(ldrow + r * 64) * IN_F + k0 + ldchunk * 8;
            asm volatile("cp.async.cg.shared.global [%0], [%1], 16;\n"
                         :: "r"(a_s + soff), "l"(ga));
        }
#pragma unroll
        for (int r = 0; r < 4; ++r) {   // B: 256 rows in 4 passes of 64
            uint32_t soff = sw128(soff0 + (uint32_t)r * 64 * 128);
            const void* gb = Bblk + (size_t)(ldrow + r * 64) * IN_F + k0 + ldchunk * 8;
            asm volatile("cp.async.cg.shared.global [%0], [%1], 16;\n"
                         :: "r"(b_s + soff), "l"(gb));
        }
    };

    const int k_tiles = IN_F / BK;   // 64

#pragma unroll
    for (int s = 0; s < STAGES - 1; ++s) {
        load_stage(s, s);
        asm volatile("cp.async.commit_group;\n");
    }

    for (int kt = 0; kt < k_tiles; ++kt) {
        asm volatile("cp.async.wait_group %0;\n" :: "n"(STAGES - 2));
        __syncthreads();

        int nkt = kt + STAGES - 1;
        if (nkt < k_tiles) load_stage(nkt % STAGES, nkt);
        asm volatile("cp.async.commit_group;\n");

        uint32_t a_s = s_base + (kt % STAGES) * STAGE_BYTES;
        uint32_t b_s = a_s + A_BYTES;

#pragma unroll
        for (int ks = 0; ks < BK / 16; ++ks) {
            uint32_t a_frag[2][4];
            uint32_t b_frag[8][2];
            int colh = ks * 16 + colh8;
#pragma unroll
            for (int mi = 0; mi < 2; ++mi) {
                int row = a_row + mi * 16;
                uint32_t addr = a_s + sw128((uint32_t)(row * 128 + colh * 2));
                asm volatile(
                    "ldmatrix.sync.aligned.m8n8.x4.shared.b16 {%0,%1,%2,%3}, [%4];\n"
                    : "=r"(a_frag[mi][0]), "=r"(a_frag[mi][1]),
                      "=r"(a_frag[mi][2]), "=r"(a_frag[mi][3])
                    : "r"(addr));
            }
#pragma unroll
            for (int ng = 0; ng < 4; ++ng) {
                int row = b_row + ng * 16;
                uint32_t addr = b_s + sw128((uint32_t)(row * 128 + colh * 2));
                uint32_t r0, r1, r2, r3;
                asm volatile(
                    "ldmatrix.sync.aligned.m8n8.x4.shared.b16 {%0,%1,%2,%3}, [%4];\n"
                    : "=r"(r0), "=r"(r1), "=r"(r2), "=r"(r3)
                    : "r"(addr));
                b_frag[2 * ng][0]     = r0;
                b_frag[2 * ng + 1][0] = r1;
                b_frag[2 * ng][1]     = r2;
                b_frag[2 * ng + 1][1] = r3;
            }
#pragma unroll
            for (int mi = 0; mi < 2; ++mi)
#pragma unroll
                for (int ni = 0; ni < 8; ++ni) {
                    asm volatile(
                        "mma.sync.aligned.m16n8k16.row.col.f32.f16.f16.f32 "
                        "{%0,%1,%2,%3}, {%4,%5,%6,%7}, {%8,%9}, {%0,%1,%2,%3};\n"
                        : "+f"(acc[mi][ni][0]), "+f"(acc[mi][ni][1]),
                          "+f"(acc[mi][ni][2]), "+f"(acc[mi][ni][3])
                        : "r"(a_frag[mi][0]), "r"(a_frag[mi][1]),
                          "r"(a_frag[mi][2]), "r"(a_frag[mi][3]),
                          "r"(b_frag[ni][0]), "r"(b_frag[ni][1]));
                }
        }
    }

    // epilogue: fp32 accumulators -> float32 output
    float* Cblk = C + (size_t)bm * BM * OUT_F + bn * BN;
#pragma unroll
    for (int mi = 0; mi < 2; ++mi)
#pragma unroll
        for (int ni = 0; ni < 8; ++ni) {
            int r0 = warp_m * 32 + mi * 16 + (lane >> 2);
            int cc = warp_n * 64 + ni * 8 + (lane & 3) * 2;
            float2 v0 = make_float2(acc[mi][ni][0], acc[mi][ni][1]);
            float2 v1 = make_float2(acc[mi][ni][2], acc[mi][ni][3]);
            *reinterpret_cast<float2*>(Cblk + (size_t)r0 * OUT_F + cc)       = v0;
            *reinterpret_cast<float2*>(Cblk + (size_t)(r0 + 8) * OUT_F + cc) = v1;
        }
}

// ---------------------------------------------------------------------------
extern "C" void kernel_launch(void* const* d_in, const int* in_sizes, int n_in,
                              void* d_out, int out_size) {
    const float* x       = (const float*)d_in[0];
    const int*   qw      = (const int*)d_in[1];
    const int*   absmax  = (const int*)d_in[2];
    const float* code    = (const float*)d_in[3];
    const float* offset  = (const float*)d_in[4];
    const float* s2a     = (const float*)d_in[5];
    const float* s2c     = (const float*)d_in[6];
    float* out = (float*)d_out;

    const size_t NA = (size_t)TOKENS * IN_F;
    convert_x_kernel<<<(int)(NA / 8 / 256), 256>>>(x);

    const int P4 = (OUT_F * IN_F / 2) / 4;
    dequant_kernel<<<P4 / 256, 256>>>(qw, absmax, code, offset, s2a, s2c);

    const int smem_bytes = STAGES * STAGE_BYTES;   // 144 KB
    cudaFuncSetAttribute(gemm_kernel,
                         cudaFuncAttributeMaxDynamicSharedMemorySize, smem_bytes);
    dim3 grid(OUT_F / BN, TOKENS / BM);            // (16, 64)
    gemm_kernel<<<grid, NTHREADS, smem_bytes>>>(out);
}